// round 7
// baseline (speedup 1.0000x reference)
#include <cuda_runtime.h>
#include <cuda_fp16.h>
#include <cstdint>

// ===================== problem constants =====================
#define NNF 128
#define NEF 64
#define NGF 64
#define HID 128
#define TGT 64

#define THREADS 384
#define GRID_X 152

// fragment tile counts
#define KT1 24   // 384/16 k-tiles, GEMM1
#define NT1 16   // 128/8  n-tiles, GEMM1 (stored; 8 used per phase)
#define KT2 8    // 128/16 k-tiles, GEMM2
#define NT2 8    // 64/8   n-tiles, GEMM2

// ===================== smem offsets (bytes) =====================
#define S_W1  0u        // 24*16*32*8 = 98304 (fp16 W1 fragments)
#define S_W2  98304u    // 8*8*32*8  = 16384
#define S_B1  114688u   // 512
#define S_B2  115200u   // 256
#define S_TOTAL 115456u

// ===================== helpers =====================
__device__ __forceinline__ uint32_t pack2h(float lo, float hi) {
    uint32_t r;
    asm("cvt.rn.f16x2.f32 %0, %1, %2;" : "=r"(r) : "f"(hi), "f"(lo));
    return r;
}
// D += A * B  (m16n8k16, fp16 in, f32 accum)
__device__ __forceinline__ void mma_f16(float* c, const uint32_t* a, uint32_t b0, uint32_t b1) {
    asm volatile("mma.sync.aligned.m16n8k16.row.col.f32.f16.f16.f32 "
        "{%0,%1,%2,%3}, {%4,%5,%6,%7}, {%8,%9}, {%0,%1,%2,%3};"
        : "+f"(c[0]), "+f"(c[1]), "+f"(c[2]), "+f"(c[3])
        : "r"(a[0]), "r"(a[1]), "r"(a[2]), "r"(a[3]), "r"(b0), "r"(b1));
}

// ===================== device scratch =====================
__device__ __align__(16) uint2 g_w1[KT1 * NT1 * 32];
__device__ __align__(16) uint2 g_w2[KT2 * NT2 * 32];
__device__ unsigned int g_counter;

// Pack W1 [384,128] and W2 [128,64] ([k][n] row-major) into per-lane m16n8k16
// B fragments (fp16): entry ((kt*NT+nt)*32+lane):
//   .x = {W[k0][n], W[k0+1][n]}, .y = {W[k0+8][n], W[k0+9][n]},
//   k0 = kt*16 + (lane&3)*2, n = nt*8 + (lane>>2).
__global__ void prep_kernel(const float* __restrict__ W1, const float* __restrict__ W2) {
    int idx = blockIdx.x * blockDim.x + threadIdx.x;
    if (idx == 0) g_counter = 0u;
    const int total1 = KT1 * NT1 * 32;
    if (idx < total1) {
        int lane = idx & 31, tile = idx >> 5;
        int nt = tile % NT1, kt = tile / NT1;
        int k0 = kt * 16 + (lane & 3) * 2;
        int n  = nt * 8 + (lane >> 2);
        float w00 = W1[(size_t)k0 * HID + n];
        float w01 = W1[(size_t)(k0 + 1) * HID + n];
        float w10 = W1[(size_t)(k0 + 8) * HID + n];
        float w11 = W1[(size_t)(k0 + 9) * HID + n];
        g_w1[idx] = make_uint2(pack2h(w00, w01), pack2h(w10, w11));
    } else if (idx < total1 + KT2 * NT2 * 32) {
        int j = idx - total1;
        int lane = j & 31, tile = j >> 5;
        int nt = tile % NT2, kt = tile / NT2;
        int k0 = kt * 16 + (lane & 3) * 2;
        int n  = nt * 8 + (lane >> 2);
        float w00 = W2[(size_t)k0 * TGT + n];
        float w01 = W2[(size_t)(k0 + 1) * TGT + n];
        float w10 = W2[(size_t)(k0 + 8) * TGT + n];
        float w11 = W2[(size_t)(k0 + 9) * TGT + n];
        g_w2[j] = make_uint2(pack2h(w00, w01), pack2h(w10, w11));
    }
}

// x pointer for k-tile kt, row r (graph g), lane column qcol
__device__ __forceinline__ const float* xptr(
    const float* __restrict__ ek, const float* __restrict__ vrk,
    const float* __restrict__ vsk, const float* __restrict__ u,
    int kt, int r, int g, int qcol) {
    const int c0 = kt * 16 + qcol;
    if (kt < 4)  return ek  + (size_t)r * NEF + c0;
    if (kt < 12) return vrk + (size_t)r * NNF + (c0 - 64);
    if (kt < 20) return vsk + (size_t)r * NNF + (c0 - 192);
    return u + (size_t)g * NGF + (c0 - 320);
}

// ===================== main fused kernel =====================
extern "C" __global__ void __launch_bounds__(THREADS, 1)
edge_mlp(const float* __restrict__ ek, const float* __restrict__ vrk,
         const float* __restrict__ vsk, const float* __restrict__ u,
         const int* __restrict__ batch,
         const float* __restrict__ b1, const float* __restrict__ b2,
         float* __restrict__ out, int ngroups) {
    extern __shared__ __align__(16) unsigned char smem[];
    const int tid = threadIdx.x;

    // -------- prologue: weight fragments + biases to smem --------
    {
        uint4* d = (uint4*)(smem + S_W1);
        const uint4* s = (const uint4*)g_w1;
        for (int i = tid; i < 98304 / 16; i += THREADS) d[i] = s[i];
        d = (uint4*)(smem + S_W2); s = (const uint4*)g_w2;
        for (int i = tid; i < 16384 / 16; i += THREADS) d[i] = s[i];
        float* b1s = (float*)(smem + S_B1);
        float* b2s = (float*)(smem + S_B2);
        if (tid < HID) b1s[tid] = b1[tid];
        if (tid < TGT) b2s[tid] = b2[tid];
    }
    __syncthreads();

    const uint2* w1 = (const uint2*)(smem + S_W1);
    const uint2* w2 = (const uint2*)(smem + S_W2);
    const float* b1s = (const float*)(smem + S_B1);
    const float* b2s = (const float*)(smem + S_B2);

    const int lane = tid & 31;
    const int qrow = lane >> 2;        // 0..7
    const int qcol = (lane & 3) * 2;   // 0,2,4,6

    // dynamic work stealing (group = 32 edge rows)
    unsigned int cur = 0xFFFFFFFFu;
    if (lane == 0) cur = atomicAdd(&g_counter, 1u);
    cur = __shfl_sync(0xFFFFFFFFu, cur, 0);

    while (cur < (unsigned)ngroups) {
        unsigned int nxt = 0xFFFFFFFFu;
        if (lane == 0) nxt = atomicAdd(&g_counter, 1u);

        const int rbase = (int)cur * 32;
        const int r00 = rbase + qrow,      r01 = r00 + 8;    // row block 0
        const int r10 = rbase + 16 + qrow, r11 = r10 + 8;    // row block 1
        const int g00 = batch[r00], g01 = batch[r01];
        const int g10 = batch[r10], g11 = batch[r11];

        float c2[64];   // GEMM2 acc: [rb][nt(8)][4]
        #pragma unroll
        for (int i = 0; i < 64; ++i) c2[i] = 0.f;

        // ============ two phases over GEMM1's N (hidden cols 0-63, 64-127) ============
        #pragma unroll 1
        for (int ph = 0; ph < 2; ++ph) {
            float acc[64];   // [rb][nt(8)][4]
            #pragma unroll
            for (int i = 0; i < 64; ++i) acc[i] = 0.f;

            // preload x for kt=0 (ek)
            float2 v[8];
            {
                const float* p;
                p = ek + (size_t)r00 * NEF + qcol; v[0] = *(const float2*)p; v[1] = *(const float2*)(p + 8);
                p = ek + (size_t)r01 * NEF + qcol; v[2] = *(const float2*)p; v[3] = *(const float2*)(p + 8);
                p = ek + (size_t)r10 * NEF + qcol; v[4] = *(const float2*)p; v[5] = *(const float2*)(p + 8);
                p = ek + (size_t)r11 * NEF + qcol; v[6] = *(const float2*)p; v[7] = *(const float2*)(p + 8);
            }

            #pragma unroll 1
            for (int kt = 0; kt < KT1; ++kt) {
                // A fragments from current v (v dead after this)
                uint32_t a0[4], a1[4];
                a0[0] = pack2h(v[0].x, v[0].y); a0[1] = pack2h(v[2].x, v[2].y);
                a0[2] = pack2h(v[1].x, v[1].y); a0[3] = pack2h(v[3].x, v[3].y);
                a1[0] = pack2h(v[4].x, v[4].y); a1[1] = pack2h(v[6].x, v[6].y);
                a1[2] = pack2h(v[5].x, v[5].y); a1[3] = pack2h(v[7].x, v[7].y);

                // prefetch kt+1 into v (consumed 16 MMAs later)
                {
                    const int kn = (kt + 1 < KT1) ? kt + 1 : KT1 - 1;
                    const float* p;
                    p = xptr(ek, vrk, vsk, u, kn, r00, g00, qcol); v[0] = *(const float2*)p; v[1] = *(const float2*)(p + 8);
                    p = xptr(ek, vrk, vsk, u, kn, r01, g01, qcol); v[2] = *(const float2*)p; v[3] = *(const float2*)(p + 8);
                    p = xptr(ek, vrk, vsk, u, kn, r10, g10, qcol); v[4] = *(const float2*)p; v[5] = *(const float2*)(p + 8);
                    p = xptr(ek, vrk, vsk, u, kn, r11, g11, qcol); v[6] = *(const float2*)p; v[7] = *(const float2*)(p + 8);
                }

                // 8 n-tiles of this phase; each B fragment reused for both row blocks
                const uint2* bw = w1 + ((size_t)kt * NT1 + ph * 8) * 32 + lane;
                #pragma unroll
                for (int nt = 0; nt < 8; ++nt) {
                    const uint2 f = bw[nt * 32];
                    mma_f16(acc + nt * 4,      a0, f.x, f.y);
                    mma_f16(acc + 32 + nt * 4, a1, f.x, f.y);
                }
            }

            // ---- bias + ReLU for this N-half ----
            #pragma unroll
            for (int nt = 0; nt < 8; ++nt) {
                const float2 bb = *(const float2*)(b1s + ph * 64 + nt * 8 + qcol);
                #pragma unroll
                for (int rb = 0; rb < 2; ++rb) {
                    float* a = acc + rb * 32 + nt * 4;
                    a[0] = fmaxf(a[0] + bb.x, 0.f);
                    a[1] = fmaxf(a[1] + bb.y, 0.f);
                    a[2] = fmaxf(a[2] + bb.x, 0.f);
                    a[3] = fmaxf(a[3] + bb.y, 0.f);
                }
            }

            // ---- GEMM2 partial accumulation over this phase's 64 h-cols ----
            #pragma unroll
            for (int j = 0; j < 4; ++j) {
                // local n-tiles 2j,2j+1 of acc == A fragment for global k-tile ph*4+j
                const float* s0 = acc + j * 8;
                const float* s1 = acc + 32 + j * 8;
                uint32_t a0[4], a1[4];
                a0[0] = pack2h(s0[0], s0[1]); a0[1] = pack2h(s0[2], s0[3]);
                a0[2] = pack2h(s0[4], s0[5]); a0[3] = pack2h(s0[6], s0[7]);
                a1[0] = pack2h(s1[0], s1[1]); a1[1] = pack2h(s1[2], s1[3]);
                a1[2] = pack2h(s1[4], s1[5]); a1[3] = pack2h(s1[6], s1[7]);

                const uint2* bw = w2 + ((size_t)(ph * 4 + j) * NT2) * 32 + lane;
                #pragma unroll
                for (int nt = 0; nt < 8; ++nt) {
                    const uint2 f = bw[nt * 32];
                    mma_f16(c2 + nt * 4,      a0, f.x, f.y);
                    mma_f16(c2 + 32 + nt * 4, a1, f.x, f.y);
                }
            }
        }

        // ================= epilogue: + b2, store fp32 (both row blocks) =================
        #pragma unroll
        for (int nt = 0; nt < 8; ++nt) {
            const float2 bb = *(const float2*)(b2s + nt * 8 + qcol);
            {
                const float* c = c2 + nt * 4;
                float2 o0, o1;
                o0.x = c[0] + bb.x; o0.y = c[1] + bb.y;
                o1.x = c[2] + bb.x; o1.y = c[3] + bb.y;
                *(float2*)(out + (size_t)r00 * TGT + nt * 8 + qcol) = o0;
                *(float2*)(out + (size_t)r01 * TGT + nt * 8 + qcol) = o1;
            }
            {
                const float* c = c2 + 32 + nt * 4;
                float2 o0, o1;
                o0.x = c[0] + bb.x; o0.y = c[1] + bb.y;
                o1.x = c[2] + bb.x; o1.y = c[3] + bb.y;
                *(float2*)(out + (size_t)r10 * TGT + nt * 8 + qcol) = o0;
                *(float2*)(out + (size_t)r11 * TGT + nt * 8 + qcol) = o1;
            }
        }

        cur = __shfl_sync(0xFFFFFFFFu, nxt, 0);
    }
}

// ===================== launch =====================
extern "C" void kernel_launch(void* const* d_in, const int* in_sizes, int n_in,
                              void* d_out, int out_size) {
    (void)n_in; (void)out_size;
    const float* ek  = (const float*)d_in[0];
    const float* vrk = (const float*)d_in[1];
    const float* vsk = (const float*)d_in[2];
    const float* u   = (const float*)d_in[3];
    const int*   batch = (const int*)d_in[4];
    const float* W1  = (const float*)d_in[5];
    const float* b1  = (const float*)d_in[6];
    const float* W2  = (const float*)d_in[7];
    const float* b2  = (const float*)d_in[8];
    float* out = (float*)d_out;

    const int E = in_sizes[0] / NEF;
    const int ngroups = E / 32;

    const int prep_total = KT1 * NT1 * 32 + KT2 * NT2 * 32;
    prep_kernel<<<(prep_total + 255) / 256, 256>>>(W1, W2);

    cudaFuncSetAttribute(edge_mlp, cudaFuncAttributeMaxDynamicSharedMemorySize, S_TOTAL);
    edge_mlp<<<GRID_X, THREADS, S_TOTAL>>>(ek, vrk, vsk, u, batch, b1, b2, out, ngroups);
}

// round 8
// speedup vs baseline: 1.1049x; 1.1049x over previous
#include <cuda_runtime.h>
#include <cuda_fp16.h>
#include <cstdint>

// ===================== problem constants =====================
#define NNF 128
#define NEF 64
#define NGF 64
#define HID 128
#define TGT 64

#define THREADS 384
#define NWARPS  12
#define GRID_X  152

// fragment tile counts
#define KT1 24   // 384/16 k-tiles, GEMM1
#define NT1 16   // 128/8  n-tiles, GEMM1 (8 per phase)
#define KT2 8    // 128/16 k-tiles, GEMM2
#define NT2 8    // 64/8   n-tiles, GEMM2

// ===================== smem offsets (bytes) =====================
#define S_W1  0u        // 24*16*32*8 = 98304 (fp16 W1 fragments)
#define S_W2  98304u    // 8*8*32*8  = 16384
#define S_B1  114688u   // 512
#define S_B2  115200u   // 256
#define S_H   115456u   // 12 warps x 8192 (per-warp h spill, A-frag layout)
#define S_TOTAL (S_H + NWARPS * 8192u)   // 213760

// ===================== helpers =====================
__device__ __forceinline__ uint32_t pack2h(float lo, float hi) {
    uint32_t r;
    asm("cvt.rn.f16x2.f32 %0, %1, %2;" : "=r"(r) : "f"(hi), "f"(lo));
    return r;
}
// D += A * B  (m16n8k16, fp16 in, f32 accum)
__device__ __forceinline__ void mma_f16(float* c, const uint32_t* a, uint32_t b0, uint32_t b1) {
    asm volatile("mma.sync.aligned.m16n8k16.row.col.f32.f16.f16.f32 "
        "{%0,%1,%2,%3}, {%4,%5,%6,%7}, {%8,%9}, {%0,%1,%2,%3};"
        : "+f"(c[0]), "+f"(c[1]), "+f"(c[2]), "+f"(c[3])
        : "r"(a[0]), "r"(a[1]), "r"(a[2]), "r"(a[3]), "r"(b0), "r"(b1));
}

// ===================== device scratch =====================
__device__ __align__(16) uint2 g_w1[KT1 * NT1 * 32];
__device__ __align__(16) uint2 g_w2[KT2 * NT2 * 32];
__device__ unsigned int g_counter;

// Pack W1 [384,128] and W2 [128,64] ([k][n] row-major) into per-lane m16n8k16
// B fragments (fp16): entry ((kt*NT+nt)*32+lane):
//   .x = {W[k0][n], W[k0+1][n]}, .y = {W[k0+8][n], W[k0+9][n]},
//   k0 = kt*16 + (lane&3)*2, n = nt*8 + (lane>>2).
__global__ void prep_kernel(const float* __restrict__ W1, const float* __restrict__ W2) {
    int idx = blockIdx.x * blockDim.x + threadIdx.x;
    if (idx == 0) g_counter = 0u;
    const int total1 = KT1 * NT1 * 32;
    if (idx < total1) {
        int lane = idx & 31, tile = idx >> 5;
        int nt = tile % NT1, kt = tile / NT1;
        int k0 = kt * 16 + (lane & 3) * 2;
        int n  = nt * 8 + (lane >> 2);
        float w00 = W1[(size_t)k0 * HID + n];
        float w01 = W1[(size_t)(k0 + 1) * HID + n];
        float w10 = W1[(size_t)(k0 + 8) * HID + n];
        float w11 = W1[(size_t)(k0 + 9) * HID + n];
        g_w1[idx] = make_uint2(pack2h(w00, w01), pack2h(w10, w11));
    } else if (idx < total1 + KT2 * NT2 * 32) {
        int j = idx - total1;
        int lane = j & 31, tile = j >> 5;
        int nt = tile % NT2, kt = tile / NT2;
        int k0 = kt * 16 + (lane & 3) * 2;
        int n  = nt * 8 + (lane >> 2);
        float w00 = W2[(size_t)k0 * TGT + n];
        float w01 = W2[(size_t)(k0 + 1) * TGT + n];
        float w10 = W2[(size_t)(k0 + 8) * TGT + n];
        float w11 = W2[(size_t)(k0 + 9) * TGT + n];
        g_w2[j] = make_uint2(pack2h(w00, w01), pack2h(w10, w11));
    }
}

// x pointer for k-tile kt, row r (graph g), lane column qcol
__device__ __forceinline__ const float* xptr(
    const float* __restrict__ ek, const float* __restrict__ vrk,
    const float* __restrict__ vsk, const float* __restrict__ u,
    int kt, int r, int g, int qcol) {
    const int c0 = kt * 16 + qcol;
    if (kt < 4)  return ek  + (size_t)r * NEF + c0;
    if (kt < 12) return vrk + (size_t)r * NNF + (c0 - 64);
    if (kt < 20) return vsk + (size_t)r * NNF + (c0 - 192);
    return u + (size_t)g * NGF + (c0 - 320);
}

// ===================== main fused kernel =====================
extern "C" __global__ void __launch_bounds__(THREADS, 1)
edge_mlp(const float* __restrict__ ek, const float* __restrict__ vrk,
         const float* __restrict__ vsk, const float* __restrict__ u,
         const int* __restrict__ batch,
         const float* __restrict__ b1, const float* __restrict__ b2,
         float* __restrict__ out, int ngroups) {
    extern __shared__ __align__(16) unsigned char smem[];
    const int tid = threadIdx.x;

    // -------- prologue: weight fragments + biases to smem --------
    {
        uint4* d = (uint4*)(smem + S_W1);
        const uint4* s = (const uint4*)g_w1;
        for (int i = tid; i < 98304 / 16; i += THREADS) d[i] = s[i];
        d = (uint4*)(smem + S_W2); s = (const uint4*)g_w2;
        for (int i = tid; i < 16384 / 16; i += THREADS) d[i] = s[i];
        float* b1s = (float*)(smem + S_B1);
        float* b2s = (float*)(smem + S_B2);
        if (tid < HID) b1s[tid] = b1[tid];
        if (tid < TGT) b2s[tid] = b2[tid];
    }
    __syncthreads();

    const uint2* w1 = (const uint2*)(smem + S_W1);
    const uint2* w2 = (const uint2*)(smem + S_W2);
    const float* b1s = (const float*)(smem + S_B1);
    const float* b2s = (const float*)(smem + S_B2);

    const int lane = tid & 31;
    const int wid  = tid >> 5;
    const int qrow = lane >> 2;        // 0..7
    const int qcol = (lane & 3) * 2;   // 0,2,4,6

    // per-warp private h spill buffer (each lane reads back only its own 16B slots)
    uint4* hbuf = (uint4*)(smem + S_H + (size_t)wid * 8192u);

    // dynamic work stealing (group = 32 edge rows)
    unsigned int cur = 0xFFFFFFFFu;
    if (lane == 0) cur = atomicAdd(&g_counter, 1u);
    cur = __shfl_sync(0xFFFFFFFFu, cur, 0);

    while (cur < (unsigned)ngroups) {
        unsigned int nxt = 0xFFFFFFFFu;
        if (lane == 0) nxt = atomicAdd(&g_counter, 1u);

        const int rbase = (int)cur * 32;
        const int r00 = rbase + qrow,      r01 = r00 + 8;    // row block 0
        const int r10 = rbase + 16 + qrow, r11 = r10 + 8;    // row block 1
        const int g00 = batch[r00], g01 = batch[r01];
        const int g10 = batch[r10], g11 = batch[r11];

        // ============ GEMM1 in two N-phases; h spilled to smem ============
        #pragma unroll 1
        for (int ph = 0; ph < 2; ++ph) {
            float acc[64];   // [rb][nt(8)][4]
            #pragma unroll
            for (int i = 0; i < 64; ++i) acc[i] = 0.f;

            // x load helper into a float2[8]
            #define LOADX(V, KT) do {                                              \
                const float* _p;                                                   \
                _p = xptr(ek, vrk, vsk, u, (KT), r00, g00, qcol);                  \
                (V)[0] = *(const float2*)_p; (V)[1] = *(const float2*)(_p + 8);    \
                _p = xptr(ek, vrk, vsk, u, (KT), r01, g01, qcol);                  \
                (V)[2] = *(const float2*)_p; (V)[3] = *(const float2*)(_p + 8);    \
                _p = xptr(ek, vrk, vsk, u, (KT), r10, g10, qcol);                  \
                (V)[4] = *(const float2*)_p; (V)[5] = *(const float2*)(_p + 8);    \
                _p = xptr(ek, vrk, vsk, u, (KT), r11, g11, qcol);                  \
                (V)[6] = *(const float2*)_p; (V)[7] = *(const float2*)(_p + 8);    \
            } while (0)

            #define CVTA(AF, V) do {                                   \
                (AF)[0] = pack2h((V)[0].x, (V)[0].y);                  \
                (AF)[1] = pack2h((V)[2].x, (V)[2].y);                  \
                (AF)[2] = pack2h((V)[1].x, (V)[1].y);                  \
                (AF)[3] = pack2h((V)[3].x, (V)[3].y);                  \
                (AF)[4] = pack2h((V)[4].x, (V)[4].y);                  \
                (AF)[5] = pack2h((V)[6].x, (V)[6].y);                  \
                (AF)[6] = pack2h((V)[5].x, (V)[5].y);                  \
                (AF)[7] = pack2h((V)[7].x, (V)[7].y);                  \
            } while (0)

            #define MMABLK(KT, AF) do {                                            \
                const uint2* _bw = w1 + ((size_t)(KT) * NT1 + ph * 8) * 32 + lane; \
                _Pragma("unroll")                                                  \
                for (int nt = 0; nt < 8; ++nt) {                                   \
                    const uint2 f = _bw[nt * 32];                                  \
                    mma_f16(acc + nt * 4,      (AF),     f.x, f.y);                \
                    mma_f16(acc + 32 + nt * 4, (AF) + 4, f.x, f.y);                \
                }                                                                  \
            } while (0)

            float2 vA[8], vB[8];
            uint32_t afA[8], afB[8];
            LOADX(vA, 0);
            LOADX(vB, 1);
            CVTA(afA, vA);

            // depth-2 pipeline, kt unrolled by 2 (12 iterations)
            #pragma unroll 1
            for (int kt = 0; kt < KT1; kt += 2) {
                const int kpre0 = (kt + 2 < KT1) ? kt + 2 : KT1 - 1;
                const int kpre1 = (kt + 3 < KT1) ? kt + 3 : KT1 - 1;
                LOADX(vA, kpre0);        // vA dead (already converted)
                MMABLK(kt, afA);         // uses kt data
                CVTA(afB, vB);           // kt+1 data, issued ~1.5 bodies ago
                LOADX(vB, kpre1);
                MMABLK(kt + 1, afB);
                CVTA(afA, vA);           // kt+2 data, issued ~1 body ago
            }

            // ---- bias + ReLU, pack, spill h to smem (A-frag layout) ----
            #pragma unroll
            for (int nt = 0; nt < 8; ++nt) {
                const float2 bb = *(const float2*)(b1s + ph * 64 + nt * 8 + qcol);
                #pragma unroll
                for (int rb = 0; rb < 2; ++rb) {
                    float* a = acc + rb * 32 + nt * 4;
                    a[0] = fmaxf(a[0] + bb.x, 0.f);
                    a[1] = fmaxf(a[1] + bb.y, 0.f);
                    a[2] = fmaxf(a[2] + bb.x, 0.f);
                    a[3] = fmaxf(a[3] + bb.y, 0.f);
                }
            }
            #pragma unroll
            for (int j = 0; j < 4; ++j) {
                const int kk = ph * 4 + j;   // global GEMM2 k-tile
                #pragma unroll
                for (int rb = 0; rb < 2; ++rb) {
                    const float* s = acc + rb * 32 + j * 8;
                    uint4 q;
                    q.x = pack2h(s[0], s[1]);
                    q.y = pack2h(s[2], s[3]);
                    q.z = pack2h(s[4], s[5]);
                    q.w = pack2h(s[6], s[7]);
                    hbuf[(kk * 2 + rb) * 32 + lane] = q;
                }
            }
            #undef LOADX
            #undef CVTA
            #undef MMABLK
        }

        // ================= GEMM2: h (smem) @ W2, 32 rows =================
        float c2[64];
        #pragma unroll
        for (int i = 0; i < 64; ++i) c2[i] = 0.f;

        #pragma unroll 1
        for (int kk = 0; kk < KT2; ++kk) {
            uint4 A0 = hbuf[(kk * 2 + 0) * 32 + lane];
            uint4 A1 = hbuf[(kk * 2 + 1) * 32 + lane];
            const uint32_t* a0 = (const uint32_t*)&A0;
            const uint32_t* a1 = (const uint32_t*)&A1;
            const uint2* bw = w2 + (size_t)kk * NT2 * 32 + lane;
            #pragma unroll
            for (int nt = 0; nt < 8; ++nt) {
                const uint2 f = bw[nt * 32];
                mma_f16(c2 + nt * 4,      a0, f.x, f.y);
                mma_f16(c2 + 32 + nt * 4, a1, f.x, f.y);
            }
        }

        // ================= epilogue: + b2, store fp32 (both row blocks) =================
        #pragma unroll
        for (int nt = 0; nt < 8; ++nt) {
            const float2 bb = *(const float2*)(b2s + nt * 8 + qcol);
            {
                const float* c = c2 + nt * 4;
                float2 o0, o1;
                o0.x = c[0] + bb.x; o0.y = c[1] + bb.y;
                o1.x = c[2] + bb.x; o1.y = c[3] + bb.y;
                *(float2*)(out + (size_t)r00 * TGT + nt * 8 + qcol) = o0;
                *(float2*)(out + (size_t)r01 * TGT + nt * 8 + qcol) = o1;
            }
            {
                const float* c = c2 + 32 + nt * 4;
                float2 o0, o1;
                o0.x = c[0] + bb.x; o0.y = c[1] + bb.y;
                o1.x = c[2] + bb.x; o1.y = c[3] + bb.y;
                *(float2*)(out + (size_t)r10 * TGT + nt * 8 + qcol) = o0;
                *(float2*)(out + (size_t)r11 * TGT + nt * 8 + qcol) = o1;
            }
        }

        cur = __shfl_sync(0xFFFFFFFFu, nxt, 0);
    }
}

// ===================== launch =====================
extern "C" void kernel_launch(void* const* d_in, const int* in_sizes, int n_in,
                              void* d_out, int out_size) {
    (void)n_in; (void)out_size;
    const float* ek  = (const float*)d_in[0];
    const float* vrk = (const float*)d_in[1];
    const float* vsk = (const float*)d_in[2];
    const float* u   = (const float*)d_in[3];
    const int*   batch = (const int*)d_in[4];
    const float* W1  = (const float*)d_in[5];
    const float* b1  = (const float*)d_in[6];
    const float* W2  = (const float*)d_in[7];
    const float* b2  = (const float*)d_in[8];
    float* out = (float*)d_out;

    const int E = in_sizes[0] / NEF;
    const int ngroups = E / 32;

    const int prep_total = KT1 * NT1 * 32 + KT2 * NT2 * 32;
    prep_kernel<<<(prep_total + 255) / 256, 256>>>(W1, W2);

    cudaFuncSetAttribute(edge_mlp, cudaFuncAttributeMaxDynamicSharedMemorySize, S_TOTAL);
    edge_mlp<<<GRID_X, THREADS, S_TOTAL>>>(ek, vrk, vsk, u, batch, b1, b2, out, ngroups);
}